// round 7
// baseline (speedup 1.0000x reference)
#include <cuda_runtime.h>
#include <math.h>

// Problem constants
#define BN    64
#define HW    784           // 28*28
#define CN    512
#define SA    28            // argmax hw splits  (HWPA = 28)
#define HWPA  28
#define SB    7             // apply hw splits   (HWPB = 112; 112*4B = 448 ≡ 0 mod 16)
#define HWPB  112
#define HWPB4 28            // HWPB / 4

// Scratch (device globals: allocation-free)
__device__ float g_pval[BN * SA * CN];
__device__ int   g_pidx[BN * SA * CN];
__device__ int   g_idx [BN * CN];

// ---------------------------------------------------------------------------
// Kernel 1: partial argmax (proven R5 config: 19.5us, DRAM 67%).
// blockIdx = (s, b); thread = channel. Coalesced scalar reads, full unroll.
// ---------------------------------------------------------------------------
__global__ void __launch_bounds__(CN)
argmax_partial_kernel(const float* __restrict__ x) {
    const int s = blockIdx.x;
    const int b = blockIdx.y;
    const int c = threadIdx.x;
    const int hw0 = s * HWPA;

    const size_t base = ((size_t)b * HW + hw0) * CN + c;

    float best = -INFINITY;
    int   bidx = hw0;

    #pragma unroll
    for (int i = 0; i < HWPA; ++i) {
        float v = x[base + (size_t)i * CN];
        if (v > best) {            // strict > + ascending i => first occurrence
            best = v;
            bidx = hw0 + i;
        }
    }

    const int o = (b * SA + s) * CN + c;
    g_pval[o] = best;
    g_pidx[o] = bidx;
}

// ---------------------------------------------------------------------------
// Kernel 2: combine 28 partials ONCE per (b,c) -> g_idx (131 KB).
// 128 blocks x 256 threads; coalesced reads. Ascending p <=> ascending hw
// start + strict > => first-occurrence tie-break (matches jnp.argmax).
// ---------------------------------------------------------------------------
__global__ void __launch_bounds__(256)
combine_kernel() {
    const int tid = blockIdx.x * 256 + threadIdx.x;   // 0 .. 32767
    const int b = tid >> 9;                           // / 512
    const int c = tid & 511;

    const size_t o0 = (size_t)b * SA * CN + c;
    float best = -INFINITY;
    int   idx  = 0;
    #pragma unroll
    for (int p = 0; p < SA; ++p) {
        float v = g_pval[o0 + (size_t)p * CN];
        if (v > best) { best = v; idx = g_pidx[o0 + (size_t)p * CN]; }
    }
    g_idx[tid] = idx;
}

// ---------------------------------------------------------------------------
// Kernel 3: apply (R2's proven shape, idx precomputed, deeper unroll).
//   out[b,hw,c] = relu(x[b,hw,c] * t_p[b, idx[b,c], hw])
// Template stream: per-thread float4 along hw. x/out: scalar coalesced
// along c. Grid (64,7)=448 blocks, 4 CTAs/SM co-resident.
// ---------------------------------------------------------------------------
__global__ void __launch_bounds__(CN)
apply_kernel(const float* __restrict__ x,
             const float* __restrict__ tp,
             float* __restrict__ out) {
    const int b = blockIdx.x;
    const int s = blockIdx.y;
    const int c = threadIdx.x;

    const int idx = g_idx[b * CN + c];    // 131 KB table, L2-hot, coalesced

    // Selected template row slice: t_p[b, idx, s*112 .. s*112+111]
    // Row pitch 3136B and slice offset 448B are 16B multiples -> float4-safe.
    const float4* __restrict__ trow4 =
        (const float4*)(tp + ((size_t)b * HW + (size_t)idx) * HW + s * HWPB);

    const size_t base = ((size_t)b * HW + (size_t)s * HWPB) * CN + c;

    #pragma unroll 7
    for (int j = 0; j < HWPB4; ++j) {
        const float4 t4 = __ldg(trow4 + j);
        const size_t o  = base + (size_t)(4 * j) * CN;

        float x0 = x[o];
        float x1 = x[o + (size_t)CN];
        float x2 = x[o + (size_t)(2 * CN)];
        float x3 = x[o + (size_t)(3 * CN)];

        out[o]                    = fmaxf(x0 * t4.x, 0.0f);
        out[o + (size_t)CN]       = fmaxf(x1 * t4.y, 0.0f);
        out[o + (size_t)(2 * CN)] = fmaxf(x2 * t4.z, 0.0f);
        out[o + (size_t)(3 * CN)] = fmaxf(x3 * t4.w, 0.0f);
    }
}

// ---------------------------------------------------------------------------
// Launch: inputs [x, t_p]; output fp32 [64,28,28,512]. Graph-capturable.
// ---------------------------------------------------------------------------
extern "C" void kernel_launch(void* const* d_in, const int* in_sizes, int n_in,
                              void* d_out, int out_size) {
    (void)in_sizes; (void)n_in; (void)out_size;
    const float* x   = (const float*)d_in[0];
    const float* tp  = (const float*)d_in[1];
    float*       out = (float*)d_out;

    dim3 gridA(SA, BN);
    argmax_partial_kernel<<<gridA, CN>>>(x);

    combine_kernel<<<128, 256>>>();

    dim3 gridB(BN, SB);
    apply_kernel<<<gridB, CN>>>(x, tp, out);
}